// round 1
// baseline (speedup 1.0000x reference)
#include <cuda_runtime.h>
#include <math.h>

#define N_ 128
#define H_ 256
#define B_ 16

// -------- device scratch (no runtime allocation allowed) --------
__device__ float g_P[H_*H_];        // W1^T W1
__device__ float g_Q[H_*H_];        // W2 W2^T
__device__ float g_W2T[N_*H_];      // W2T[i*H+h] = W2[h*N+i]
__device__ float g_s[B_*H_];        // sech^2(u)
__device__ float g_c[B_*H_];        // -2 tanh(u) sech^2(u)
__device__ float g_Avec[B_*N_];
__device__ float g_Cvec[B_*N_];
__device__ float g_vn[B_];
__device__ float g_A2[B_*H_*H_];    // per-sample A2 = P S Q
__device__ float g_part[B_*16];     // per-tile partial sums of nrm^2/2

// -------- kernel 0a: transpose W2 --------
__global__ void k_transpose(const float* __restrict__ W2){
    int idx = blockIdx.x*blockDim.x + threadIdx.x;
    if (idx < N_*H_){
        int i = idx / H_, h = idx % H_;
        g_W2T[idx] = W2[h*N_ + i];
    }
}

// -------- kernel 0b: P = W1^T W1 and Q = W2 W2^T (via W2T) --------
__global__ void k_PQ(const float* __restrict__ W1){
    int g = blockIdx.x;           // 0..255
    int h = threadIdx.x;          // 0..255
    const float* src = (blockIdx.y == 0) ? W1 : g_W2T;   // both [N_, H_] row-major
    float acc = 0.f;
    #pragma unroll 8
    for (int k = 0; k < N_; k++)
        acc += src[k*H_ + g] * src[k*H_ + h];
    if (blockIdx.y == 0) g_P[g*H_ + h] = acc;
    else                 g_Q[g*H_ + h] = acc;
}

// -------- kernel 1: per-sample vector pipeline --------
__global__ void k_vectors(const float* __restrict__ tptr,
                          const float* __restrict__ state,
                          const float* __restrict__ x0,
                          const float* __restrict__ x1,
                          const float* __restrict__ W1,
                          const float* __restrict__ b1,
                          const float* __restrict__ W2){
    int b = blockIdx.x, tid = threadIdx.x;   // 256 threads
    __shared__ float xs[N_], vs[N_];
    __shared__ float sw[H_], cwy[H_], pv[H_], cwz[H_];
    __shared__ float red[H_];

    float tval = *tptr;
    float window = 4.f * tval * (1.f - tval);
    if (tid < N_){
        float dev = state[b*N_ + tid];
        float v   = state[(B_+b)*N_ + tid];
        float x0v = x0[b*N_ + tid];
        xs[tid] = x0v + tval*(x1[b*N_ + tid] - x0v) + window*dev;
        vs[tid] = v;
        red[tid] = v*v;
    } else {
        red[tid] = 0.f;
    }
    __syncthreads();

    int h = tid;
    float u = b1[h], w = 0.f, y = 0.f;
    #pragma unroll 8
    for (int k = 0; k < N_; k++){
        float w1 = W1[k*H_ + h];
        u += xs[k]*w1;
        y += vs[k]*w1;
        w += g_W2T[k*H_ + h]*vs[k];
    }
    float th = tanhf(u);
    float s  = 1.f - th*th;
    float c  = -2.f*th*s;
    g_s[b*H_ + h] = s;
    g_c[b*H_ + h] = c;
    sw[h]  = s*w;
    cwy[h] = c*w*y;
    __syncthreads();

    // z = P(s .* w), q2 = P(c .* w .* y) -- use P symmetry for coalesced reads
    float z = 0.f, q2 = 0.f;
    #pragma unroll 8
    for (int a = 0; a < H_; a++){
        float pa = g_P[a*H_ + h];
        z  += pa*sw[a];
        q2 += pa*cwy[a];
    }
    pv[h]  = c*y*z + s*q2;
    cwz[h] = c*w*z;
    __syncthreads();

    // ||v|| reduction
    for (int st = 128; st > 0; st >>= 1){
        if (tid < st) red[tid] += red[tid + st];
        __syncthreads();
    }
    if (tid == 0) g_vn[b] = sqrtf(red[0]);

    // A = W2^T pv ; C = 2 * W1 cwz
    if (tid < N_){
        int i = tid;
        float A = 0.f, C = 0.f;
        #pragma unroll 8
        for (int hh = 0; hh < H_; hh++){
            A += W2[hh*N_ + i] * pv[hh];
            C += W1[i*H_ + hh] * cwz[hh];
        }
        g_Avec[b*N_ + i] = A;
        g_Cvec[b*N_ + i] = 2.f*C;
    }
}

// -------- kernel 2: A2[b] = P * diag(s_b) * Q   (64x64 tiles, 4x4 micro) --------
__global__ void k_A2(){
    int b  = blockIdx.z;
    int g0 = blockIdx.y*64, h0 = blockIdx.x*64;
    __shared__ float Ps[16][64];
    __shared__ float Qs[16][64];
    int tid = threadIdx.x;
    int ty = tid >> 4, tx = tid & 15;
    float acc[4][4];
    #pragma unroll
    for (int i = 0; i < 4; i++)
        #pragma unroll
        for (int j = 0; j < 4; j++) acc[i][j] = 0.f;

    const float* sb = g_s + b*H_;
    for (int a0 = 0; a0 < H_; a0 += 16){
        #pragma unroll
        for (int it = 0; it < 4; it++){
            int l = tid + it*256;
            int a = l >> 6, gg = l & 63;
            // P symmetric: P[g, a] = P[a, g] -> coalesced row reads
            Ps[a][gg] = g_P[(a0+a)*H_ + g0 + gg];
            Qs[a][gg] = g_Q[(a0+a)*H_ + h0 + gg] * sb[a0+a];
        }
        __syncthreads();
        #pragma unroll
        for (int a = 0; a < 16; a++){
            float ra[4], rb[4];
            #pragma unroll
            for (int i = 0; i < 4; i++) ra[i] = Ps[a][ty*4 + i];
            #pragma unroll
            for (int j = 0; j < 4; j++) rb[j] = Qs[a][tx*4 + j];
            #pragma unroll
            for (int i = 0; i < 4; i++)
                #pragma unroll
                for (int j = 0; j < 4; j++) acc[i][j] += ra[i]*rb[j];
        }
        __syncthreads();
    }
    float* dst = g_A2 + b*H_*H_;
    #pragma unroll
    for (int i = 0; i < 4; i++){
        int g = g0 + ty*4 + i;
        #pragma unroll
        for (int j = 0; j < 4; j++)
            dst[g*H_ + h0 + tx*4 + j] = acc[i][j];
    }
}

// -------- kernel 3: A1 = A2 * diag(s) * P, fused with nrm^2 reduction --------
// partial = sum_{g,h in tile} c_g c_h P_gh (Q_gh A1_gh + A2_gh A2_hg)
__global__ void k_nrm(){
    int b  = blockIdx.z;
    int g0 = blockIdx.y*64, h0 = blockIdx.x*64;
    __shared__ float As[16][65];   // padded: written with a-fast index
    __shared__ float Bs[16][64];
    int tid = threadIdx.x;
    int ty = tid >> 4, tx = tid & 15;
    float acc[4][4];
    #pragma unroll
    for (int i = 0; i < 4; i++)
        #pragma unroll
        for (int j = 0; j < 4; j++) acc[i][j] = 0.f;

    const float* A2b = g_A2 + b*H_*H_;
    const float* sb  = g_s + b*H_;
    for (int a0 = 0; a0 < H_; a0 += 16){
        #pragma unroll
        for (int it = 0; it < 4; it++){
            int l = tid + it*256;
            {   int gg = l >> 4, a = l & 15;
                As[a][gg] = A2b[(g0+gg)*H_ + a0 + a] * sb[a0+a]; }
            {   int a = l >> 6, hh = l & 63;
                Bs[a][hh] = g_P[(a0+a)*H_ + h0 + hh]; }
        }
        __syncthreads();
        #pragma unroll
        for (int a = 0; a < 16; a++){
            float ra[4], rb[4];
            #pragma unroll
            for (int i = 0; i < 4; i++) ra[i] = As[a][ty*4 + i];
            #pragma unroll
            for (int j = 0; j < 4; j++) rb[j] = Bs[a][tx*4 + j];
            #pragma unroll
            for (int i = 0; i < 4; i++)
                #pragma unroll
                for (int j = 0; j < 4; j++) acc[i][j] += ra[i]*rb[j];
        }
        __syncthreads();
    }

    const float* cb = g_c + b*H_;
    float local = 0.f;
    #pragma unroll
    for (int i = 0; i < 4; i++){
        int g = g0 + ty*4 + i;
        float cg = cb[g];
        #pragma unroll
        for (int j = 0; j < 4; j++){
            int h = h0 + tx*4 + j;
            float pg  = g_P[g*H_ + h];
            float qg  = g_Q[g*H_ + h];
            float a2  = A2b[g*H_ + h];
            float a2t = A2b[h*H_ + g];
            local += cg*cb[h]*pg*(qg*acc[i][j] + a2*a2t);
        }
    }
    __shared__ float red[256];
    red[tid] = local;
    __syncthreads();
    for (int st = 128; st > 0; st >>= 1){
        if (tid < st) red[tid] += red[tid + st];
        __syncthreads();
    }
    if (tid == 0) g_part[b*16 + blockIdx.y*4 + blockIdx.x] = red[0];
}

// -------- kernel 4: finalize output --------
__global__ void k_final(const float* __restrict__ state, float* __restrict__ out){
    int b = blockIdx.x, tid = threadIdx.x;   // 128 threads
    __shared__ float nrm_s;
    if (tid == 0){
        float sum = 0.f;
        #pragma unroll
        for (int i = 0; i < 16; i++) sum += g_part[b*16 + i];   // deterministic order
        nrm_s = sqrtf(fmaxf(2.f*sum, 0.f));
    }
    __syncthreads();
    float nrm = nrm_s;
    float vn  = g_vn[b];
    float v   = state[(B_+b)*N_ + tid];
    float dev = state[b*N_ + tid];
    float a = -(g_Avec[b*N_ + tid] - 0.5f*g_Cvec[b*N_ + tid])
              / ((nrm + 1e-6f) * (vn + 1e-6f));
    out[b*N_ + tid]       = v;
    out[(B_+b)*N_ + tid]  = a - 0.1f*dev;
}

// -------- launch --------
extern "C" void kernel_launch(void* const* d_in, const int* in_sizes, int n_in,
                              void* d_out, int out_size){
    const float* t     = (const float*)d_in[0];
    const float* state = (const float*)d_in[1];
    const float* x0    = (const float*)d_in[2];
    const float* x1    = (const float*)d_in[3];
    const float* W1    = (const float*)d_in[4];
    const float* b1    = (const float*)d_in[5];
    const float* W2    = (const float*)d_in[6];
    float* out = (float*)d_out;

    k_transpose<<<(N_*H_ + 255)/256, 256>>>(W2);
    k_PQ<<<dim3(H_, 2), H_>>>(W1);
    k_vectors<<<B_, H_>>>(t, state, x0, x1, W1, b1, W2);
    k_A2<<<dim3(4, 4, B_), 256>>>();
    k_nrm<<<dim3(4, 4, B_), 256>>>();
    k_final<<<B_, N_>>>(state, out);
}